// round 1
// baseline (speedup 1.0000x reference)
#include <cuda_runtime.h>
#include <math.h>

#define NN 100000
#define EE 220000
#define NBG 4096
#define HIDD 256
#define INF_F 3.4e38f
#define BN_SC 0.999995000037499687f  // 1/sqrt(1+1e-5)

// ---------------- scratch (device globals; no allocations allowed) ----------
__device__ float g_h[NN * 256];
__device__ float g_xl[NN * 256];
__device__ float g_xr[NN * 256];
__device__ float g_tmp[NN * 128];
__device__ float g_gate[NN];
__device__ float g_pooled[NBG * 256];
__device__ float g_r1[NBG * 256];
__device__ float g_r2[NBG * 128];
__device__ float g_r3[NBG * 64];
__device__ float g_easum[16];
__device__ float g_eself[4 * 256];
__device__ int   g_deg[NN];
__device__ int   g_cnt[NN];
__device__ int   g_rowptr[NN + 1];
__device__ int   g_eid[EE];
__device__ int   g_gcnt[NBG];
__device__ int   g_gptr[NBG + 1];
__device__ int   g_bsum[1024];

// ---------------- SGEMM: C = A(MxK) * B(KxN) (+bias, epilogue) --------------
// EPI: 0 none, 1 elu(v*BN), 2 relu(v), 3 relu(v*BN)
template <int EPI>
__global__ void sgemm_k(const float* __restrict__ A, const float* __restrict__ Bm,
                        const float* __restrict__ bias, float* __restrict__ C,
                        int M, int Ncol, int K) {
    __shared__ float As[16][129];
    __shared__ float Bs[16][64];
    int tid = threadIdx.x;
    int row0 = blockIdx.x * 128;
    int col0 = blockIdx.y * 64;
    int tx = tid & 15, ty = tid >> 4;
    float acc[8][4];
#pragma unroll
    for (int i = 0; i < 8; i++)
#pragma unroll
        for (int j = 0; j < 4; j++) acc[i][j] = 0.f;

    int ktiles = (K + 15) / 16;
    for (int kt = 0; kt < ktiles; kt++) {
        int k0 = kt * 16;
#pragma unroll
        for (int i = 0; i < 8; i++) {
            int t = tid + i * 256;
            int rr = t >> 4, kk = t & 15;
            int gr = row0 + rr, gk = k0 + kk;
            As[kk][rr] = (gr < M && gk < K) ? A[gr * K + gk] : 0.f;
        }
#pragma unroll
        for (int i = 0; i < 4; i++) {
            int t = tid + i * 256;
            int kk = t >> 6, cc = t & 63;
            int gk = k0 + kk, gc = col0 + cc;
            Bs[kk][cc] = (gk < K && gc < Ncol) ? Bm[gk * Ncol + gc] : 0.f;
        }
        __syncthreads();
#pragma unroll
        for (int k = 0; k < 16; k++) {
            float a[8], b[4];
#pragma unroll
            for (int i = 0; i < 8; i++) a[i] = As[k][ty * 8 + i];
            float4 bb = *(const float4*)&Bs[k][tx * 4];
            b[0] = bb.x; b[1] = bb.y; b[2] = bb.z; b[3] = bb.w;
#pragma unroll
            for (int i = 0; i < 8; i++)
#pragma unroll
                for (int j = 0; j < 4; j++) acc[i][j] += a[i] * b[j];
        }
        __syncthreads();
    }
#pragma unroll
    for (int i = 0; i < 8; i++) {
        int r = row0 + ty * 8 + i;
        if (r >= M) continue;
#pragma unroll
        for (int j = 0; j < 4; j++) {
            int c = col0 + tx * 4 + j;
            if (c >= Ncol) continue;
            float v = acc[i][j];
            if (bias) v += bias[c];
            if (EPI == 1) { v *= BN_SC; v = v > 0.f ? v : (expf(v) - 1.f); }
            else if (EPI == 2) { v = v > 0.f ? v : 0.f; }
            else if (EPI == 3) { v *= BN_SC; v = v > 0.f ? v : 0.f; }
            C[r * Ncol + c] = v;
        }
    }
}

// ---------------- graph prep kernels ---------------------------------------
__global__ void easum_k(const float* __restrict__ ea) {
    __shared__ float s[10];
    if (threadIdx.x < 10) s[threadIdx.x] = 0.f;
    __syncthreads();
    float loc[10];
#pragma unroll
    for (int d = 0; d < 10; d++) loc[d] = 0.f;
    for (int e = blockIdx.x * 256 + threadIdx.x; e < EE; e += gridDim.x * 256) {
#pragma unroll
        for (int d = 0; d < 10; d++) loc[d] += ea[e * 10 + d];
    }
#pragma unroll
    for (int d = 0; d < 10; d++) atomicAdd(&s[d], loc[d]);
    __syncthreads();
    if (threadIdx.x < 10) atomicAdd(&g_easum[threadIdx.x], s[threadIdx.x]);
}

__global__ void eself_k(const float* __restrict__ We) {
    int l = blockIdx.x, j = threadIdx.x;
    float s = 0.f;
#pragma unroll
    for (int d = 0; d < 10; d++)
        s += (g_easum[d] * (1.0f / EE)) * We[l * 2560 + d * 256 + j];
    g_eself[l * 256 + j] = s;
}

__global__ void cnt_deg_k(const int* __restrict__ tgt) {
    int e = blockIdx.x * 256 + threadIdx.x;
    if (e < EE) atomicAdd(&g_deg[tgt[e]], 1);
}
__global__ void scatter_k(const int* __restrict__ tgt) {
    int e = blockIdx.x * 256 + threadIdx.x;
    if (e < EE) {
        int t = tgt[e];
        int pos = g_rowptr[t] + atomicAdd(&g_cnt[t], 1);
        g_eid[pos] = e;
    }
}
__global__ void cnt_graph_k(const int* __restrict__ batch) {
    int n = blockIdx.x * 256 + threadIdx.x;
    if (n < NN) atomicAdd(&g_gcnt[batch[n]], 1);
}

// exclusive scan: per-block (1024), block sums, add-back
__global__ void scan1_k(const int* __restrict__ in, int* __restrict__ out,
                        int* __restrict__ bsum, int n) {
    __shared__ int sm[1024];
    int i = blockIdx.x * 1024 + threadIdx.x;
    int v = (i < n) ? in[i] : 0;
    sm[threadIdx.x] = v;
    __syncthreads();
    for (int off = 1; off < 1024; off <<= 1) {
        int t = (threadIdx.x >= off) ? sm[threadIdx.x - off] : 0;
        __syncthreads();
        sm[threadIdx.x] += t;
        __syncthreads();
    }
    if (i < n) out[i] = sm[threadIdx.x] - v;
    if (threadIdx.x == 1023) bsum[blockIdx.x] = sm[1023];
}
__global__ void scan2_k(int* __restrict__ bsum, int nb) {
    __shared__ int sm[1024];
    int v = (threadIdx.x < nb) ? bsum[threadIdx.x] : 0;
    sm[threadIdx.x] = v;
    __syncthreads();
    for (int off = 1; off < 1024; off <<= 1) {
        int t = (threadIdx.x >= off) ? sm[threadIdx.x - off] : 0;
        __syncthreads();
        sm[threadIdx.x] += t;
        __syncthreads();
    }
    if (threadIdx.x < nb) bsum[threadIdx.x] = sm[threadIdx.x] - v;
}
__global__ void scan3_k(int* __restrict__ out, const int* __restrict__ bsum,
                        int n, int total) {
    int i = blockIdx.x * 1024 + threadIdx.x;
    if (i < n) out[i] += bsum[blockIdx.x];
    if (i == 0) out[n] = total;
}

// ---------------- fused GATv2 layer (warp per node, online softmax) --------
__global__ void gat_k(float* __restrict__ h, const float* __restrict__ xl,
                      const float* __restrict__ xr,
                      const int* __restrict__ rowptr, const int* __restrict__ eid,
                      const int* __restrict__ src, const float* __restrict__ eattr,
                      const float* __restrict__ We, const float* __restrict__ attw,
                      const float* __restrict__ bgat, const float* __restrict__ eself) {
    __shared__ float sWe[2560];
    __shared__ float sAtt[256];
    int tid = threadIdx.x;
    for (int i = tid; i < 2560; i += 256) sWe[i] = We[i];
    sAtt[tid] = attw[tid];
    __syncthreads();
    int lane = tid & 31, w = tid >> 5;
    int n = blockIdx.x * 8 + w;
    if (n >= NN) return;

    float xrv[8], attv[8], acc[8], mm[8], ss[8];
#pragma unroll
    for (int hh = 0; hh < 8; hh++) {
        xrv[hh]  = xr[n * 256 + hh * 32 + lane];
        attv[hh] = sAtt[hh * 32 + lane];
        acc[hh] = 0.f; mm[hh] = -INF_F; ss[hh] = 0.f;
    }
    int jb = rowptr[n], je = rowptr[n + 1];
    for (int j = jb; j <= je; j++) {   // j == je handles the implicit self-loop
        bool selfloop = (j == je);
        int sidx;
        float ea[10];
        if (!selfloop) {
            int e = eid[j];
            sidx = src[e];
#pragma unroll
            for (int d = 0; d < 10; d++) ea[d] = eattr[e * 10 + d];
        } else {
            sidx = n;
        }
#pragma unroll
        for (int hh = 0; hh < 8; hh++) {
            float xlv = xl[sidx * 256 + hh * 32 + lane];
            float ep;
            if (!selfloop) {
                ep = 0.f;
#pragma unroll
                for (int d = 0; d < 10; d++) ep += ea[d] * sWe[d * 256 + hh * 32 + lane];
            } else {
                ep = eself[hh * 32 + lane];
            }
            float t = xlv + xrv[hh] + ep;
            t = t > 0.f ? t : 0.2f * t;          // LeakyReLU(0.2)
            float p = t * attv[hh];
#pragma unroll
            for (int o = 16; o > 0; o >>= 1) p += __shfl_xor_sync(0xffffffffu, p, o);
            float l = p;                          // logit, same on all lanes
            if (l > mm[hh]) {
                float f = expf(mm[hh] - l);
                ss[hh] *= f; acc[hh] *= f; mm[hh] = l;
            }
            float wgt = expf(l - mm[hh]);
            ss[hh] += wgt;
            acc[hh] += wgt * xlv;
        }
    }
#pragma unroll
    for (int hh = 0; hh < 8; hh++) {
        float o = acc[hh] / ss[hh];
        float v = (o + bgat[hh * 32 + lane]) * BN_SC;
        v = v > 0.f ? v : (expf(v) - 1.f);        // ELU
        int idx = n * 256 + hh * 32 + lane;
        h[idx] = v + h[idx];                      // residual, in place
    }
}

// ---------------- gate dot (warp/node), pooling (block/graph), final -------
__global__ void gate_k(const float* __restrict__ t, const float* __restrict__ Wg2,
                       const float* __restrict__ bg2, float* __restrict__ gate) {
    int lane = threadIdx.x & 31, w = threadIdx.x >> 5;
    int n = blockIdx.x * 8 + w;
    if (n >= NN) return;
    float s = 0.f;
#pragma unroll
    for (int k = 0; k < 4; k++) s += t[n * 128 + k * 32 + lane] * Wg2[k * 32 + lane];
#pragma unroll
    for (int o = 16; o > 0; o >>= 1) s += __shfl_xor_sync(0xffffffffu, s, o);
    if (lane == 0) gate[n] = s + bg2[0];
}

__global__ void pool_k(const float* __restrict__ h, const float* __restrict__ gate,
                       const int* __restrict__ gptr, float* __restrict__ pooled) {
    int b = blockIdx.x;
    int s0 = gptr[b], s1 = gptr[b + 1];
    __shared__ float red[256];
    int tid = threadIdx.x;
    float m = -INF_F;
    for (int i = s0 + tid; i < s1; i += 256) m = fmaxf(m, gate[i]);
    red[tid] = m; __syncthreads();
    for (int o = 128; o > 0; o >>= 1) { if (tid < o) red[tid] = fmaxf(red[tid], red[tid + o]); __syncthreads(); }
    float gmax = red[0]; __syncthreads();
    float s = 0.f;
    for (int i = s0 + tid; i < s1; i += 256) s += expf(gate[i] - gmax);
    red[tid] = s; __syncthreads();
    for (int o = 128; o > 0; o >>= 1) { if (tid < o) red[tid] += red[tid + o]; __syncthreads(); }
    float inv = 1.f / (red[0] + 1e-16f);
    float acc = 0.f;
    for (int i = s0; i < s1; i++) acc += expf(gate[i] - gmax) * inv * h[i * 256 + tid];
    pooled[b * 256 + tid] = acc;
}

__global__ void final_k(const float* __restrict__ r3, const float* __restrict__ W4,
                        const float* __restrict__ b4, float* __restrict__ out) {
    int lane = threadIdx.x & 31, w = threadIdx.x >> 5;
    int b = blockIdx.x * 8 + w;
    if (b >= NBG) return;
    float s = r3[b * 64 + lane] * W4[lane] + r3[b * 64 + 32 + lane] * W4[32 + lane];
#pragma unroll
    for (int o = 16; o > 0; o >>= 1) s += __shfl_xor_sync(0xffffffffu, s, o);
    if (lane == 0) out[b] = s + b4[0];
}

// ---------------- launch ----------------------------------------------------
extern "C" void kernel_launch(void* const* d_in, const int* in_sizes, int n_in,
                              void* d_out, int out_size) {
    const float* x    = (const float*)d_in[0];
    const int*   ei   = (const int*)d_in[1];
    const float* eattr= (const float*)d_in[2];
    const int*   batch= (const int*)d_in[3];
    const float* W_in = (const float*)d_in[4];
    const float* b_in = (const float*)d_in[5];
    const float* Wl   = (const float*)d_in[6];
    const float* Wr   = (const float*)d_in[7];
    const float* We   = (const float*)d_in[8];
    const float* att  = (const float*)d_in[9];
    const float* bgat = (const float*)d_in[10];
    const float* Wg1  = (const float*)d_in[11];
    const float* bg1  = (const float*)d_in[12];
    const float* Wg2  = (const float*)d_in[13];
    const float* bg2  = (const float*)d_in[14];
    const float* W1   = (const float*)d_in[15];
    const float* b1   = (const float*)d_in[16];
    const float* W2   = (const float*)d_in[17];
    const float* b2   = (const float*)d_in[18];
    const float* W3   = (const float*)d_in[19];
    const float* b3   = (const float*)d_in[20];
    const float* W4   = (const float*)d_in[21];
    const float* b4   = (const float*)d_in[22];
    float* out = (float*)d_out;
    const int* srcp = ei;
    const int* tgtp = ei + EE;

    static bool init = false;
    static float *ph, *pxl, *pxr, *ptmp, *pgate, *ppool, *pr1, *pr2, *pr3, *peasum, *peself;
    static int *pdeg, *pcnt, *prow, *peid, *pgcnt, *pgptr, *pbsum;
    if (!init) {
        cudaGetSymbolAddress((void**)&ph, g_h);
        cudaGetSymbolAddress((void**)&pxl, g_xl);
        cudaGetSymbolAddress((void**)&pxr, g_xr);
        cudaGetSymbolAddress((void**)&ptmp, g_tmp);
        cudaGetSymbolAddress((void**)&pgate, g_gate);
        cudaGetSymbolAddress((void**)&ppool, g_pooled);
        cudaGetSymbolAddress((void**)&pr1, g_r1);
        cudaGetSymbolAddress((void**)&pr2, g_r2);
        cudaGetSymbolAddress((void**)&pr3, g_r3);
        cudaGetSymbolAddress((void**)&peasum, g_easum);
        cudaGetSymbolAddress((void**)&peself, g_eself);
        cudaGetSymbolAddress((void**)&pdeg, g_deg);
        cudaGetSymbolAddress((void**)&pcnt, g_cnt);
        cudaGetSymbolAddress((void**)&prow, g_rowptr);
        cudaGetSymbolAddress((void**)&peid, g_eid);
        cudaGetSymbolAddress((void**)&pgcnt, g_gcnt);
        cudaGetSymbolAddress((void**)&pgptr, g_gptr);
        cudaGetSymbolAddress((void**)&pbsum, g_bsum);
        init = true;
    }

    cudaMemsetAsync(pdeg, 0, NN * sizeof(int), 0);
    cudaMemsetAsync(pcnt, 0, NN * sizeof(int), 0);
    cudaMemsetAsync(pgcnt, 0, NBG * sizeof(int), 0);
    cudaMemsetAsync(peasum, 0, 16 * sizeof(float), 0);

    // edge-attr mean -> per-layer self-loop edge projection
    easum_k<<<128, 256>>>(eattr);
    eself_k<<<4, 256>>>(We);

    // CSR by target
    cnt_deg_k<<<(EE + 255) / 256, 256>>>(tgtp);
    scan1_k<<<(NN + 1023) / 1024, 1024>>>(pdeg, prow, pbsum, NN);
    scan2_k<<<1, 1024>>>(pbsum, (NN + 1023) / 1024);
    scan3_k<<<(NN + 1023) / 1024, 1024>>>(prow, pbsum, NN, EE);
    scatter_k<<<(EE + 255) / 256, 256>>>(tgtp);

    // graph ranges (batch is sorted)
    cnt_graph_k<<<(NN + 255) / 256, 256>>>(batch);
    scan1_k<<<(NBG + 1023) / 1024, 1024>>>(pgcnt, pgptr, pbsum, NBG);
    scan2_k<<<1, 1024>>>(pbsum, (NBG + 1023) / 1024);
    scan3_k<<<(NBG + 1023) / 1024, 1024>>>(pgptr, pbsum, NBG, NN);

    dim3 gN256((NN + 127) / 128, 4);
    dim3 gN128((NN + 127) / 128, 2);
    dim3 gB256((NBG + 127) / 128, 4);
    dim3 gB128((NBG + 127) / 128, 2);
    dim3 gB64((NBG + 127) / 128, 1);

    // input projection: elu((x @ W_in + b_in) * BN)
    sgemm_k<1><<<gN256, 256>>>(x, W_in, b_in, ph, NN, 256, 75);

    for (int l = 0; l < 4; l++) {
        sgemm_k<0><<<gN256, 256>>>(ph, Wl + l * 65536, nullptr, pxl, NN, 256, 256);
        sgemm_k<0><<<gN256, 256>>>(ph, Wr + l * 65536, nullptr, pxr, NN, 256, 256);
        gat_k<<<NN / 8, 256>>>(ph, pxl, pxr, prow, peid, srcp, eattr,
                               We + l * 2560, att + l * 256, bgat + l * 256,
                               peself + l * 256);
    }

    // GlobalAttention pooling
    sgemm_k<2><<<gN128, 256>>>(ph, Wg1, bg1, ptmp, NN, 128, 256);
    gate_k<<<NN / 8, 256>>>(ptmp, Wg2, bg2, pgate);
    pool_k<<<NBG, 256>>>(ph, pgate, pgptr, ppool);

    // readout MLP
    sgemm_k<3><<<gB256, 256>>>(ppool, W1, b1, pr1, NBG, 256, 256);
    sgemm_k<3><<<gB128, 256>>>(pr1, W2, b2, pr2, NBG, 128, 256);
    sgemm_k<2><<<gB64, 256>>>(pr2, W3, b3, pr3, NBG, 64, 128);
    final_k<<<NBG / 8, 256>>>(pr3, W4, b4, out);
}